// round 14
// baseline (speedup 1.0000x reference)
#include <cuda_runtime.h>
#include <cuda_bf16.h>
#include <cstdint>

#define M_DIM 128
#define D_DIM 16
#define W_DIM 15
#define POS   (W_DIM*W_DIM*W_DIM*W_DIM)   // 50625
#define BATCH 4
#define ROWS  (BATCH*POS)                  // 202500
#define TILE_M 64
#define TILES ((ROWS + TILE_M - 1) / TILE_M)   // 3165
#define PADROWS (TILES * TILE_M)               // 202560
#define GRID_GEMM 456                          // 3 CTAs/SM x 152 SMs
#define NSTRIPS (BATCH * W_DIM * W_DIM)        // 900 (b,k1,k2) strips

// Allocation-free scratch (__device__ globals)
__device__ float         g_nk[256 * M_DIM];
__device__ __nv_bfloat16 g_Eh[M_DIM * M_DIM];             // bf16(M - I)
__device__ __nv_bfloat16 g_Ah[(size_t)PADROWS * M_DIM];   // pooled hi
__device__ __nv_bfloat16 g_Al[(size_t)PADROWS * M_DIM];   // pooled lo

// ---------------------------------------------------------------------------
__device__ __forceinline__ uint32_t smem_u32(const void* p) {
    uint32_t a;
    asm("{ .reg .u64 t; cvta.to.shared.u64 t, %1; cvt.u32.u64 %0, t; }"
        : "=r"(a) : "l"(p));
    return a;
}
__device__ __forceinline__ uint32_t pack_bf16(__nv_bfloat16 a, __nv_bfloat16 b) {
    return ((uint32_t)__bfloat16_as_ushort(b) << 16) | __bfloat16_as_ushort(a);
}
__device__ __forceinline__ float2 bf16x2_to_f2(uint32_t v) {
    __nv_bfloat162 b;
    *(uint32_t*)&b = v;
    return __bfloat1622float2(b);
}
__device__ __forceinline__ void mma_bf16(float* c, const uint32_t* a, const uint32_t* b) {
    asm volatile(
        "mma.sync.aligned.m16n8k16.row.col.f32.bf16.bf16.f32 "
        "{%0,%1,%2,%3}, {%4,%5,%6,%7}, {%8,%9}, {%0,%1,%2,%3};"
        : "+f"(c[0]), "+f"(c[1]), "+f"(c[2]), "+f"(c[3])
        : "r"(a[0]), "r"(a[1]), "r"(a[2]), "r"(a[3]), "r"(b[0]), "r"(b[1]));
}
__device__ __forceinline__ void ldm_x4(uint32_t (&r)[4], uint32_t addr) {
    asm volatile("ldmatrix.sync.aligned.m8n8.x4.shared.b16 {%0,%1,%2,%3}, [%4];"
        : "=r"(r[0]), "=r"(r[1]), "=r"(r[2]), "=r"(r[3]) : "r"(addr));
}
#define CP_ASYNC_CG(dst, src) \
    asm volatile("cp.async.cg.shared.global [%0], [%1], 16;" \
                 :: "r"(dst), "l"(src) : "memory")
#define CP_ASYNC_COMMIT() asm volatile("cp.async.commit_group;" ::: "memory")
#define CP_ASYNC_WAIT1()  asm volatile("cp.async.wait_group 1;" ::: "memory")

// ---------------------------------------------------------------------------
// Pool with 2-D rolling window reuse + folded prep.
// warp -> (strip, c3-segment, channel-half). Strip = one (b,k1,k2); within it
// P(c3,j) = 4-corner (d1,d2) plane sum; R(j) ring gives k3-direction reuse.
// Read amplification 4.8x (vs 8.53x in the 1-D rolling version).
// Blocks 0..206 also build Nk, E = bf16(M - I), and zero padded rows.
// ---------------------------------------------------------------------------
__global__ void __launch_bounds__(256)
pool_kernel(const float2* __restrict__ vec,
            const float* __restrict__ Acoeff,
            const float* __restrict__ Bbasis,
            const float* __restrict__ Mmat) {
    const int t = threadIdx.x;

    if (blockIdx.x < 207) {              // folded prep: 207*256 = 52992
        int e = blockIdx.x * 256 + t;
        if (e < 32768) {
            int idx = e >> 7, j = e & 127;
            g_nk[e] = Acoeff[j * 256 + idx] * Bbasis[idx * M_DIM + j];
        } else if (e < 49152) {
            int e2 = e - 32768;                    // 0..16383
            int r = e2 >> 7, c = e2 & 127;
            float v = Mmat[e2] - (r == c ? 1.0f : 0.0f);
            g_Eh[e2] = __float2bfloat16_rn(v);
        } else {                                   // zero padded rows
            int z = e - 49152;                     // 0..3839
            int row = ROWS + (z >> 6);
            int w = z & 63;
            if (w < 32) ((uint2*)g_Ah)[(size_t)row * 32 + w] = make_uint2(0u, 0u);
            else        ((uint2*)g_Al)[(size_t)row * 32 + (w - 32)] = make_uint2(0u, 0u);
        }
    }

    const int lane = t & 31;
    const int wg   = blockIdx.x * 8 + (t >> 5);    // 0..3599
    const int half = wg & 1;
    const int seg  = (wg >> 1) & 1;
    const int strip = wg >> 2;                     // 0..899
    if (strip >= NSTRIPS) return;

    int k2 = strip % W_DIM;
    int r1 = strip / W_DIM;
    int k1 = r1 % W_DIM;
    int b  = r1 / W_DIM;

    const int c = half * 32 + lane;                // channel-pair 0..63
    // strides in float2 units
    const int S4 = 64, S3 = 1024, S2 = 16384, S1 = 262144;
    const long long SB = (long long)S1 * D_DIM;
    const float2* base = vec + (long long)b * SB + (long long)k1 * S1
                             + (long long)k2 * S2 + c;

    const int c3lo = seg ? 8 : 0;
    const int nk3  = seg ? 7 : 8;                  // k3 count in this segment
    const int row_strip = strip * 225;

    uint32_t* outH = (uint32_t*)g_Ah;
    uint32_t* outL = (uint32_t*)g_Al;

    float2 R[15];
    for (int ci = 0; ci <= nk3; ci++) {
        const int c3 = c3lo + ci;
        const float2* pc = base + c3 * S3;
        float2 Pprev;
#pragma unroll
        for (int j = 0; j < 16; j++) {
            const float2* pj = pc + j * S4;
            float2 v0 = __ldg(pj);
            float2 v1 = __ldg(pj + S1);
            float2 v2 = __ldg(pj + S2);
            float2 v3 = __ldg(pj + S1 + S2);
            float2 P;
            P.x = (v0.x + v1.x) + (v2.x + v3.x);
            P.y = (v0.y + v1.y) + (v2.y + v3.y);
            if (j > 0) {
                float2 Rn;
                Rn.x = Pprev.x + P.x;
                Rn.y = Pprev.y + P.y;
                if (ci > 0) {
                    float px = (R[j - 1].x + Rn.x) * 0.0625f;
                    float py = (R[j - 1].y + Rn.y) * 0.0625f;
                    int row = row_strip + (c3 - 1) * W_DIM + (j - 1);
                    __nv_bfloat16 hx = __float2bfloat16_rn(px);
                    __nv_bfloat16 hy = __float2bfloat16_rn(py);
                    __nv_bfloat16 lx = __float2bfloat16_rn(px - __bfloat162float(hx));
                    __nv_bfloat16 ly = __float2bfloat16_rn(py - __bfloat162float(hy));
                    outH[(size_t)row * 64 + c] = pack_bf16(hx, hy);
                    outL[(size_t)row * 64 + c] = pack_bf16(lx, ly);
                }
                R[j - 1] = Rn;
            }
            Pprev = P;
        }
    }
}

// ---------------------------------------------------------------------------
// Persistent GEMM (round-11 verbatim, proven at 58us):
// acc = A_hi @ E^T (1 bf16 pass); out = Nk - (Ahi+Alo) - acc.
// E once/CTA; A_hi K-halves double-pumped; smem-staged coalesced epilogue.
// ---------------------------------------------------------------------------
#define PITCH_B   272
#define PITCH_A   144
#define PITCH_ST  132
#define OFF_E     0
#define OFF_A0    (128 * PITCH_B)              // 34816
#define OFF_A1    (OFF_A0 + TILE_M * PITCH_A)  // 44032
#define OFF_ST    (OFF_A1 + TILE_M * PITCH_A)  // 53248
#define SMEM_TOTAL (OFF_ST + 32 * PITCH_ST * 4) // 70144

__device__ __forceinline__ void load_a_half(uint32_t sb, int tile, int h, int t) {
    const uint32_t base = (h ? OFF_A1 : OFF_A0);
    const char* ah = (const char*)g_Ah;
    const size_t rowbase = (size_t)tile * TILE_M;
#pragma unroll
    for (int i = 0; i < 2; i++) {
        int e = t + i * 256;            // 0..511
        int r = e >> 3, c = e & 7;      // row 0..63, 16B chunk 0..7
        uint32_t dst = sb + base + (uint32_t)(r * PITCH_A + c * 16);
        size_t src = (rowbase + r) * 256 + (size_t)h * 128 + c * 16;
        CP_ASYNC_CG(dst, ah + src);
    }
}

__global__ void __launch_bounds__(256, 3)
gemm_kernel(float* __restrict__ out) {
    extern __shared__ char smem[];
    const uint32_t sb = smem_u32(smem);
    const int t    = threadIdx.x;
    const int wid  = t >> 5;
    const int lane = t & 31;
    const int wm = wid & 1;
    const int wn = wid >> 1;

    int tile = blockIdx.x;
    {   // prologue: E (once) + first tile's A halves
        const char* eh = (const char*)g_Eh;
#pragma unroll
        for (int i = 0; i < 8; i++) {                  // 2048 chunks
            int e = t + i * 256;
            int r = e >> 4, c = e & 15;
            CP_ASYNC_CG(sb + OFF_E + (uint32_t)(r * PITCH_B + c * 16),
                        eh + r * 256 + c * 16);
        }
        load_a_half(sb, tile, 0, t);
        CP_ASYNC_COMMIT();                             // G: E + A0(t0)
        load_a_half(sb, tile, 1, t);
        CP_ASYNC_COMMIT();                             // G: A1(t0)
    }

    const uint32_t eHi = sb + OFF_E
        + (uint32_t)((wn * 32 + (lane & 7) + (lane >> 4) * 8) * PITCH_B
                     + ((lane >> 3) & 1) * 16);
    const uint32_t a0Frag = sb + OFF_A0
        + (uint32_t)((wm * 32 + (lane & 15)) * PITCH_A + (lane >> 4) * 16);
    const uint32_t a1Frag = a0Frag + (OFF_A1 - OFF_A0);

    const int g  = lane >> 2;
    const int cq = (lane & 3) * 2;

    const char* ahB = (const char*)g_Ah;
    const char* alB = (const char*)g_Al;

    for (; tile < TILES; tile += GRID_GEMM) {
        const int next = tile + GRID_GEMM;
        float acc[2][4][4];
#pragma unroll
        for (int mt = 0; mt < 2; mt++)
#pragma unroll
            for (int nt = 0; nt < 4; nt++)
#pragma unroll
                for (int i = 0; i < 4; i++) acc[mt][nt][i] = 0.f;

        // ---- half 0 (K 0..63) ----
        CP_ASYNC_WAIT1();
        __syncthreads();
#pragma unroll
        for (int ks = 0; ks < 4; ks++) {
            const uint32_t koff = ks * 32;
            uint32_t ah[2][4], ehf[2][4];
            ldm_x4(ah[0], a0Frag + koff);
            ldm_x4(ah[1], a0Frag + 16 * PITCH_A + koff);
            ldm_x4(ehf[0], eHi + koff);
            ldm_x4(ehf[1], eHi + 16 * PITCH_B + koff);
#pragma unroll
            for (int mt = 0; mt < 2; mt++)
#pragma unroll
                for (int nt = 0; nt < 4; nt++)
                    mma_bf16(acc[mt][nt], ah[mt], &ehf[nt >> 1][(nt & 1) * 2]);
        }
        __syncthreads();                       // all warps done reading A0
        if (next < TILES) load_a_half(sb, next, 0, t);
        CP_ASYNC_COMMIT();

        // ---- half 1 (K 64..127) ----
        CP_ASYNC_WAIT1();
        __syncthreads();
#pragma unroll
        for (int ks = 0; ks < 4; ks++) {
            const uint32_t koff = ks * 32;
            const uint32_t kb   = 128 + ks * 32;
            uint32_t ah[2][4], ehf[2][4];
            ldm_x4(ah[0], a1Frag + koff);
            ldm_x4(ah[1], a1Frag + 16 * PITCH_A + koff);
            ldm_x4(ehf[0], eHi + kb);
            ldm_x4(ehf[1], eHi + 16 * PITCH_B + kb);
#pragma unroll
            for (int mt = 0; mt < 2; mt++)
#pragma unroll
                for (int nt = 0; nt < 4; nt++)
                    mma_bf16(acc[mt][nt], ah[mt], &ehf[nt >> 1][(nt & 1) * 2]);
        }
        __syncthreads();                       // all warps done reading A1
        if (next < TILES) load_a_half(sb, next, 1, t);
        CP_ASYNC_COMMIT();

        // ---- epilogue: two 32-row phases; smem-staged, coalesced ----
        const int row0 = tile * TILE_M;
#pragma unroll
        for (int phase = 0; phase < 2; phase++) {
            if (wm == phase) {                 // stage this warp's rows
#pragma unroll
                for (int mt = 0; mt < 2; mt++)
#pragma unroll
                    for (int h8 = 0; h8 < 2; h8++) {
                        int br = mt * 16 + g + h8 * 8;   // 0..31 buffer row
#pragma unroll
                        for (int nt = 0; nt < 4; nt++) {
                            float2 v;
                            v.x = acc[mt][nt][h8 * 2 + 0];
                            v.y = acc[mt][nt][h8 * 2 + 1];
                            *(float2*)(smem + OFF_ST
                                + (br * PITCH_ST + wn * 32 + nt * 8 + cq) * 4) = v;
                        }
                    }
            }
            __syncthreads();
#pragma unroll
            for (int i = 0; i < 2; i++) {
                int e = t + i * 256;           // 0..511
                int r32 = e >> 4, c = e & 15;
                int row = row0 + phase * 32 + r32;
                if (row < ROWS) {
                    int pos = row % POS;
                    int k4 = pos % W_DIM;
                    int q1 = pos / W_DIM;
                    int k3 = q1 % W_DIM;
                    int q2 = q1 / W_DIM;
                    int k2 = q2 % W_DIM;
                    int k1 = q2 / W_DIM;
                    int idx = (((k1 & 3) * 4 + (k2 & 3)) * 4 + (k3 & 3)) * 4
                              + (k4 & 3);
                    const float* nkp = g_nk + idx * M_DIM + c * 8;
                    float4 nk0 = __ldg((const float4*)nkp);
                    float4 nk1 = __ldg((const float4*)(nkp + 4));
                    uint4 ph = __ldg((const uint4*)(ahB + (size_t)row * 256 + c * 16));
                    uint4 pl = __ldg((const uint4*)(alB + (size_t)row * 256 + c * 16));
                    const float* st = (const float*)(smem + OFF_ST
                                        + (r32 * PITCH_ST + c * 8) * 4);
                    float2 h0 = bf16x2_to_f2(ph.x), l0 = bf16x2_to_f2(pl.x);
                    float2 h1 = bf16x2_to_f2(ph.y), l1 = bf16x2_to_f2(pl.y);
                    float2 h2 = bf16x2_to_f2(ph.z), l2 = bf16x2_to_f2(pl.z);
                    float2 h3 = bf16x2_to_f2(ph.w), l3 = bf16x2_to_f2(pl.w);
                    float4 o0, o1;
                    o0.x = nk0.x - (h0.x + l0.x) - st[0];
                    o0.y = nk0.y - (h0.y + l0.y) - st[1];
                    o0.z = nk0.z - (h1.x + l1.x) - st[2];
                    o0.w = nk0.w - (h1.y + l1.y) - st[3];
                    o1.x = nk1.x - (h2.x + l2.x) - st[4];
                    o1.y = nk1.y - (h2.y + l2.y) - st[5];
                    o1.z = nk1.z - (h3.x + l3.x) - st[6];
                    o1.w = nk1.w - (h3.y + l3.y) - st[7];
                    float* op = out + (size_t)row * M_DIM + c * 8;
                    *(float4*)op = o0;
                    *(float4*)(op + 4) = o1;
                }
            }
            __syncthreads();                   // buffer reuse by next phase
        }
    }
}

// ---------------------------------------------------------------------------
extern "C" void kernel_launch(void* const* d_in, const int* in_sizes, int n_in,
                              void* d_out, int out_size) {
    const float* vec    = (const float*)d_in[0];   // (4,16,16,16,16,128)
    const float* Mmat   = (const float*)d_in[1];   // (128,128)
    const float* Acoeff = (const float*)d_in[2];   // (128,256)
    const float* Bbasis = (const float*)d_in[3];   // (256,128)
    float* out = (float*)d_out;                    // (4, 50625, 128)

    cudaFuncSetAttribute(gemm_kernel,
                         cudaFuncAttributeMaxDynamicSharedMemorySize,
                         SMEM_TOTAL);

    pool_kernel<<<450, 256>>>((const float2*)vec, Acoeff, Bbasis, Mmat);
    gemm_kernel<<<GRID_GEMM, 256, SMEM_TOTAL>>>(out);
}

// round 15
// speedup vs baseline: 1.3107x; 1.3107x over previous
#include <cuda_runtime.h>
#include <cuda_bf16.h>
#include <cstdint>

#define M_DIM 128
#define D_DIM 16
#define W_DIM 15
#define POS   (W_DIM*W_DIM*W_DIM*W_DIM)   // 50625
#define BATCH 4
#define ROWS  (BATCH*POS)                  // 202500
#define TILE_M 64
#define TILES ((ROWS + TILE_M - 1) / TILE_M)   // 3165
#define PADROWS (TILES * TILE_M)               // 202560
#define GRID_GEMM 456                          // 3 CTAs/SM x 152 SMs

// Allocation-free scratch (__device__ globals)
__device__ float         g_nk[256 * M_DIM];
__device__ __nv_bfloat16 g_Eh[M_DIM * M_DIM];             // bf16(M - I)
__device__ __nv_bfloat16 g_Ah[(size_t)PADROWS * M_DIM];   // pooled hi
__device__ __nv_bfloat16 g_Al[(size_t)PADROWS * M_DIM];   // pooled lo

// ---------------------------------------------------------------------------
__device__ __forceinline__ uint32_t smem_u32(const void* p) {
    uint32_t a;
    asm("{ .reg .u64 t; cvta.to.shared.u64 t, %1; cvt.u32.u64 %0, t; }"
        : "=r"(a) : "l"(p));
    return a;
}
__device__ __forceinline__ uint32_t pack_bf16(__nv_bfloat16 a, __nv_bfloat16 b) {
    return ((uint32_t)__bfloat16_as_ushort(b) << 16) | __bfloat16_as_ushort(a);
}
__device__ __forceinline__ void split2(float x, float y, uint32_t& hi, uint32_t& lo) {
    __nv_bfloat16 hx = __float2bfloat16_rn(x);
    __nv_bfloat16 hy = __float2bfloat16_rn(y);
    __nv_bfloat16 lx = __float2bfloat16_rn(x - __bfloat162float(hx));
    __nv_bfloat16 ly = __float2bfloat16_rn(y - __bfloat162float(hy));
    hi = pack_bf16(hx, hy);
    lo = pack_bf16(lx, ly);
}
__device__ __forceinline__ float2 bf16x2_to_f2(uint32_t v) {
    __nv_bfloat162 b;
    *(uint32_t*)&b = v;
    return __bfloat1622float2(b);
}
__device__ __forceinline__ void mma_bf16(float* c, const uint32_t* a, const uint32_t* b) {
    asm volatile(
        "mma.sync.aligned.m16n8k16.row.col.f32.bf16.bf16.f32 "
        "{%0,%1,%2,%3}, {%4,%5,%6,%7}, {%8,%9}, {%0,%1,%2,%3};"
        : "+f"(c[0]), "+f"(c[1]), "+f"(c[2]), "+f"(c[3])
        : "r"(a[0]), "r"(a[1]), "r"(a[2]), "r"(a[3]), "r"(b[0]), "r"(b[1]));
}
__device__ __forceinline__ void ldm_x4(uint32_t (&r)[4], uint32_t addr) {
    asm volatile("ldmatrix.sync.aligned.m8n8.x4.shared.b16 {%0,%1,%2,%3}, [%4];"
        : "=r"(r[0]), "=r"(r[1]), "=r"(r[2]), "=r"(r[3]) : "r"(addr));
}
#define CP_ASYNC_CG(dst, src) \
    asm volatile("cp.async.cg.shared.global [%0], [%1], 16;" \
                 :: "r"(dst), "l"(src) : "memory")
#define CP_ASYNC_COMMIT() asm volatile("cp.async.commit_group;" ::: "memory")
#define CP_ASYNC_WAIT1()  asm volatile("cp.async.wait_group 1;" ::: "memory")

// ---------------------------------------------------------------------------
// Pool (round-11 proven form + folded prep): warp = 8-row chunk,
// lane = 16B channel chunk; run-streaming within the chunk.
// Blocks 0..191 also build the Nk table and E = bf16(M - I).
// Pooled stores use __stcs: streaming, keeps L2 for vec read-reuse.
// ---------------------------------------------------------------------------
__global__ void __launch_bounds__(256)
pool_kernel(const float4* __restrict__ vec,
            const float* __restrict__ Acoeff,
            const float* __restrict__ Bbasis,
            const float* __restrict__ Mmat) {
    const int t = threadIdx.x;

    if (blockIdx.x < 192) {
        int e = blockIdx.x * 256 + t;
        if (e < 32768) {
            int idx = e >> 7, j = e & 127;
            g_nk[e] = Acoeff[j * 256 + idx] * Bbasis[idx * M_DIM + j];
        } else {
            int e2 = e - 32768;                    // 0..16383
            int r = e2 >> 7, c = e2 & 127;
            float v = Mmat[e2] - (r == c ? 1.0f : 0.0f);
            g_Eh[e2] = __float2bfloat16_rn(v);
        }
    }

    const int lane = t & 31;
    const int sub  = t >> 5;
    const int q    = lane;
    int r    = blockIdx.x * 64 + sub * 8;
    int rend = r + 8;

    for (int rr = (r < ROWS ? ROWS : r); rr < rend; rr++) {
        uint2 z = make_uint2(0u, 0u);
        __stcs(((uint2*)g_Ah) + (size_t)rr * 32 + q, z);
        __stcs(((uint2*)g_Al) + (size_t)rr * 32 + q, z);
    }
    int gend = rend < ROWS ? rend : ROWS;

    const int S4 = 32, S3 = 512, S2 = 8192, S1 = 131072;  // float4 strides
    const long long SBATCH = (long long)S1 * D_DIM;

    while (r < gend) {
        int b   = r / POS;
        int pos = r - b * POS;
        int k4  = pos % W_DIM;
        int r1  = pos / W_DIM;
        int k3  = r1 % W_DIM;
        int r2  = r1 / W_DIM;
        int k2  = r2 % W_DIM;
        int k1  = r2 / W_DIM;
        int segend = r + (W_DIM - k4);
        if (segend > gend) segend = gend;
        const int L = segend - r;

        const float4* p = vec + b * SBATCH + k1 * S1 + k2 * S2
                              + k3 * S3 + k4 * S4 + q;
        const int co1 = S3, co2 = S2, co3 = S2 + S3;
        const int co4 = S1, co5 = S1 + S3, co6 = S1 + S2, co7 = S1 + S2 + S3;

        float4 sp;
        {
            float sx = 0.f, sy = 0.f, sz = 0.f, sw = 0.f;
            float4 v;
            v = __ldg(p);        sx += v.x; sy += v.y; sz += v.z; sw += v.w;
            v = __ldg(p + co1);  sx += v.x; sy += v.y; sz += v.z; sw += v.w;
            v = __ldg(p + co2);  sx += v.x; sy += v.y; sz += v.z; sw += v.w;
            v = __ldg(p + co3);  sx += v.x; sy += v.y; sz += v.z; sw += v.w;
            v = __ldg(p + co4);  sx += v.x; sy += v.y; sz += v.z; sw += v.w;
            v = __ldg(p + co5);  sx += v.x; sy += v.y; sz += v.z; sw += v.w;
            v = __ldg(p + co6);  sx += v.x; sy += v.y; sz += v.z; sw += v.w;
            v = __ldg(p + co7);  sx += v.x; sy += v.y; sz += v.z; sw += v.w;
            sp = make_float4(sx, sy, sz, sw);
        }
        for (int j = 1; j <= L; j++) {
            const float4* pj = p + j * S4;
            float sx = 0.f, sy = 0.f, sz = 0.f, sw = 0.f;
            float4 v;
            v = __ldg(pj);       sx += v.x; sy += v.y; sz += v.z; sw += v.w;
            v = __ldg(pj + co1); sx += v.x; sy += v.y; sz += v.z; sw += v.w;
            v = __ldg(pj + co2); sx += v.x; sy += v.y; sz += v.z; sw += v.w;
            v = __ldg(pj + co3); sx += v.x; sy += v.y; sz += v.z; sw += v.w;
            v = __ldg(pj + co4); sx += v.x; sy += v.y; sz += v.z; sw += v.w;
            v = __ldg(pj + co5); sx += v.x; sy += v.y; sz += v.z; sw += v.w;
            v = __ldg(pj + co6); sx += v.x; sy += v.y; sz += v.z; sw += v.w;
            v = __ldg(pj + co7); sx += v.x; sy += v.y; sz += v.z; sw += v.w;

            float ox = (sp.x + sx) * 0.0625f;
            float oy = (sp.y + sy) * 0.0625f;
            float oz = (sp.z + sz) * 0.0625f;
            float ow = (sp.w + sw) * 0.0625f;
            sp = make_float4(sx, sy, sz, sw);

            uint2 hv, lv;
            split2(ox, oy, hv.x, lv.x);
            split2(oz, ow, hv.y, lv.y);
            size_t orow = (size_t)(r + j - 1) * 32 + q;
            __stcs(((uint2*)g_Ah) + orow, hv);
            __stcs(((uint2*)g_Al) + orow, lv);
        }
        r = segend;
    }
}

// ---------------------------------------------------------------------------
// Persistent GEMM (round-11 proven): acc = A_hi @ E^T (1 bf16 pass);
// out = Nk - (Ahi+Alo) - acc. E once/CTA; A_hi K-halves double-pumped;
// smem-staged coalesced epilogue. Epilogue gmem: __ldcs reads, __stcs writes.
// ---------------------------------------------------------------------------
#define PITCH_B   272
#define PITCH_A   144
#define PITCH_ST  132
#define OFF_E     0
#define OFF_A0    (128 * PITCH_B)              // 34816
#define OFF_A1    (OFF_A0 + TILE_M * PITCH_A)  // 44032
#define OFF_ST    (OFF_A1 + TILE_M * PITCH_A)  // 53248
#define SMEM_TOTAL (OFF_ST + 32 * PITCH_ST * 4) // 70144

__device__ __forceinline__ void load_a_half(uint32_t sb, int tile, int h, int t) {
    const uint32_t base = (h ? OFF_A1 : OFF_A0);
    const char* ah = (const char*)g_Ah;
    const size_t rowbase = (size_t)tile * TILE_M;
#pragma unroll
    for (int i = 0; i < 2; i++) {
        int e = t + i * 256;            // 0..511
        int r = e >> 3, c = e & 7;      // row 0..63, 16B chunk 0..7
        uint32_t dst = sb + base + (uint32_t)(r * PITCH_A + c * 16);
        size_t src = (rowbase + r) * 256 + (size_t)h * 128 + c * 16;
        CP_ASYNC_CG(dst, ah + src);
    }
}

__global__ void __launch_bounds__(256, 3)
gemm_kernel(float* __restrict__ out) {
    extern __shared__ char smem[];
    const uint32_t sb = smem_u32(smem);
    const int t    = threadIdx.x;
    const int wid  = t >> 5;
    const int lane = t & 31;
    const int wm = wid & 1;
    const int wn = wid >> 1;

    int tile = blockIdx.x;
    {   // prologue: E (once) + first tile's A halves
        const char* eh = (const char*)g_Eh;
#pragma unroll
        for (int i = 0; i < 8; i++) {                  // 2048 chunks
            int e = t + i * 256;
            int r = e >> 4, c = e & 15;
            CP_ASYNC_CG(sb + OFF_E + (uint32_t)(r * PITCH_B + c * 16),
                        eh + r * 256 + c * 16);
        }
        load_a_half(sb, tile, 0, t);
        CP_ASYNC_COMMIT();                             // G: E + A0(t0)
        load_a_half(sb, tile, 1, t);
        CP_ASYNC_COMMIT();                             // G: A1(t0)
    }

    const uint32_t eHi = sb + OFF_E
        + (uint32_t)((wn * 32 + (lane & 7) + (lane >> 4) * 8) * PITCH_B
                     + ((lane >> 3) & 1) * 16);
    const uint32_t a0Frag = sb + OFF_A0
        + (uint32_t)((wm * 32 + (lane & 15)) * PITCH_A + (lane >> 4) * 16);
    const uint32_t a1Frag = a0Frag + (OFF_A1 - OFF_A0);

    const int g  = lane >> 2;
    const int cq = (lane & 3) * 2;

    const char* ahB = (const char*)g_Ah;
    const char* alB = (const char*)g_Al;

    for (; tile < TILES; tile += GRID_GEMM) {
        const int next = tile + GRID_GEMM;
        float acc[2][4][4];
#pragma unroll
        for (int mt = 0; mt < 2; mt++)
#pragma unroll
            for (int nt = 0; nt < 4; nt++)
#pragma unroll
                for (int i = 0; i < 4; i++) acc[mt][nt][i] = 0.f;

        // ---- half 0 (K 0..63) ----
        CP_ASYNC_WAIT1();
        __syncthreads();
#pragma unroll
        for (int ks = 0; ks < 4; ks++) {
            const uint32_t koff = ks * 32;
            uint32_t ah[2][4], ehf[2][4];
            ldm_x4(ah[0], a0Frag + koff);
            ldm_x4(ah[1], a0Frag + 16 * PITCH_A + koff);
            ldm_x4(ehf[0], eHi + koff);
            ldm_x4(ehf[1], eHi + 16 * PITCH_B + koff);
#pragma unroll
            for (int mt = 0; mt < 2; mt++)
#pragma unroll
                for (int nt = 0; nt < 4; nt++)
                    mma_bf16(acc[mt][nt], ah[mt], &ehf[nt >> 1][(nt & 1) * 2]);
        }
        __syncthreads();                       // all warps done reading A0
        if (next < TILES) load_a_half(sb, next, 0, t);
        CP_ASYNC_COMMIT();

        // ---- half 1 (K 64..127) ----
        CP_ASYNC_WAIT1();
        __syncthreads();
#pragma unroll
        for (int ks = 0; ks < 4; ks++) {
            const uint32_t koff = ks * 32;
            const uint32_t kb   = 128 + ks * 32;
            uint32_t ah[2][4], ehf[2][4];
            ldm_x4(ah[0], a1Frag + koff);
            ldm_x4(ah[1], a1Frag + 16 * PITCH_A + koff);
            ldm_x4(ehf[0], eHi + kb);
            ldm_x4(ehf[1], eHi + 16 * PITCH_B + kb);
#pragma unroll
            for (int mt = 0; mt < 2; mt++)
#pragma unroll
                for (int nt = 0; nt < 4; nt++)
                    mma_bf16(acc[mt][nt], ah[mt], &ehf[nt >> 1][(nt & 1) * 2]);
        }
        __syncthreads();                       // all warps done reading A1
        if (next < TILES) load_a_half(sb, next, 1, t);
        CP_ASYNC_COMMIT();

        // ---- epilogue: two 32-row phases; smem-staged, coalesced ----
        const int row0 = tile * TILE_M;
#pragma unroll
        for (int phase = 0; phase < 2; phase++) {
            if (wm == phase) {                 // stage this warp's rows
#pragma unroll
                for (int mt = 0; mt < 2; mt++)
#pragma unroll
                    for (int h8 = 0; h8 < 2; h8++) {
                        int br = mt * 16 + g + h8 * 8;   // 0..31 buffer row
#pragma unroll
                        for (int nt = 0; nt < 4; nt++) {
                            float2 v;
                            v.x = acc[mt][nt][h8 * 2 + 0];
                            v.y = acc[mt][nt][h8 * 2 + 1];
                            *(float2*)(smem + OFF_ST
                                + (br * PITCH_ST + wn * 32 + nt * 8 + cq) * 4) = v;
                        }
                    }
            }
            __syncthreads();
#pragma unroll
            for (int i = 0; i < 2; i++) {
                int e = t + i * 256;           // 0..511
                int r32 = e >> 4, c = e & 15;
                int row = row0 + phase * 32 + r32;
                if (row < ROWS) {
                    int pos = row % POS;
                    int k4 = pos % W_DIM;
                    int q1 = pos / W_DIM;
                    int k3 = q1 % W_DIM;
                    int q2 = q1 / W_DIM;
                    int k2 = q2 % W_DIM;
                    int k1 = q2 / W_DIM;
                    int idx = (((k1 & 3) * 4 + (k2 & 3)) * 4 + (k3 & 3)) * 4
                              + (k4 & 3);
                    const float* nkp = g_nk + idx * M_DIM + c * 8;
                    float4 nk0 = __ldg((const float4*)nkp);
                    float4 nk1 = __ldg((const float4*)(nkp + 4));
                    uint4 ph = __ldcs((const uint4*)(ahB + (size_t)row * 256 + c * 16));
                    uint4 pl = __ldcs((const uint4*)(alB + (size_t)row * 256 + c * 16));
                    const float* st = (const float*)(smem + OFF_ST
                                        + (r32 * PITCH_ST + c * 8) * 4);
                    float2 h0 = bf16x2_to_f2(ph.x), l0 = bf16x2_to_f2(pl.x);
                    float2 h1 = bf16x2_to_f2(ph.y), l1 = bf16x2_to_f2(pl.y);
                    float2 h2 = bf16x2_to_f2(ph.z), l2 = bf16x2_to_f2(pl.z);
                    float2 h3 = bf16x2_to_f2(ph.w), l3 = bf16x2_to_f2(pl.w);
                    float4 o0, o1;
                    o0.x = nk0.x - (h0.x + l0.x) - st[0];
                    o0.y = nk0.y - (h0.y + l0.y) - st[1];
                    o0.z = nk0.z - (h1.x + l1.x) - st[2];
                    o0.w = nk0.w - (h1.y + l1.y) - st[3];
                    o1.x = nk1.x - (h2.x + l2.x) - st[4];
                    o1.y = nk1.y - (h2.y + l2.y) - st[5];
                    o1.z = nk1.z - (h3.x + l3.x) - st[6];
                    o1.w = nk1.w - (h3.y + l3.y) - st[7];
                    float* op = out + (size_t)row * M_DIM + c * 8;
                    __stcs((float4*)op, o0);
                    __stcs((float4*)(op + 4), o1);
                }
            }
            __syncthreads();                   // buffer reuse by next phase
        }
    }
}

// ---------------------------------------------------------------------------
extern "C" void kernel_launch(void* const* d_in, const int* in_sizes, int n_in,
                              void* d_out, int out_size) {
    const float* vec    = (const float*)d_in[0];   // (4,16,16,16,16,128)
    const float* Mmat   = (const float*)d_in[1];   // (128,128)
    const float* Acoeff = (const float*)d_in[2];   // (128,256)
    const float* Bbasis = (const float*)d_in[3];   // (256,128)
    float* out = (float*)d_out;                    // (4, 50625, 128)

    cudaFuncSetAttribute(gemm_kernel,
                         cudaFuncAttributeMaxDynamicSharedMemorySize,
                         SMEM_TOTAL);

    pool_kernel<<<TILES, 256>>>((const float4*)vec, Acoeff, Bbasis, Mmat);
    gemm_kernel<<<GRID_GEMM, 256, SMEM_TOTAL>>>(out);
}

// round 16
// speedup vs baseline: 1.3304x; 1.0150x over previous
#include <cuda_runtime.h>
#include <cuda_bf16.h>
#include <cstdint>

#define M_DIM 128
#define D_DIM 16
#define W_DIM 15
#define POS   (W_DIM*W_DIM*W_DIM*W_DIM)   // 50625
#define BATCH 4
#define ROWS  (BATCH*POS)                  // 202500
#define TILE_M 64
#define TILES ((ROWS + TILE_M - 1) / TILE_M)   // 3165
#define PADROWS (TILES * TILE_M)               // 202560
#define GRID_GEMM 456                          // 3 CTAs/SM x 152 SMs
#define NRUNS (BATCH * W_DIM * W_DIM * W_DIM)  // 13500 runs of 15 rows
#define GRID_POOL ((NRUNS + 7) / 8)            // 1688

// Allocation-free scratch (__device__ globals)
__device__ float         g_nk[256 * M_DIM];
__device__ __nv_bfloat16 g_Eh[M_DIM * M_DIM];             // bf16(M - I)
__device__ __nv_bfloat16 g_Ah[(size_t)PADROWS * M_DIM];   // pooled hi
__device__ __nv_bfloat16 g_Al[(size_t)PADROWS * M_DIM];   // pooled lo

// ---------------------------------------------------------------------------
__device__ __forceinline__ uint32_t smem_u32(const void* p) {
    uint32_t a;
    asm("{ .reg .u64 t; cvta.to.shared.u64 t, %1; cvt.u32.u64 %0, t; }"
        : "=r"(a) : "l"(p));
    return a;
}
__device__ __forceinline__ uint32_t pack_bf16(__nv_bfloat16 a, __nv_bfloat16 b) {
    return ((uint32_t)__bfloat16_as_ushort(b) << 16) | __bfloat16_as_ushort(a);
}
__device__ __forceinline__ void split2(float x, float y, uint32_t& hi, uint32_t& lo) {
    __nv_bfloat16 hx = __float2bfloat16_rn(x);
    __nv_bfloat16 hy = __float2bfloat16_rn(y);
    __nv_bfloat16 lx = __float2bfloat16_rn(x - __bfloat162float(hx));
    __nv_bfloat16 ly = __float2bfloat16_rn(y - __bfloat162float(hy));
    hi = pack_bf16(hx, hy);
    lo = pack_bf16(lx, ly);
}
__device__ __forceinline__ float2 bf16x2_to_f2(uint32_t v) {
    __nv_bfloat162 b;
    *(uint32_t*)&b = v;
    return __bfloat1622float2(b);
}
__device__ __forceinline__ void mma_bf16(float* c, const uint32_t* a, const uint32_t* b) {
    asm volatile(
        "mma.sync.aligned.m16n8k16.row.col.f32.bf16.bf16.f32 "
        "{%0,%1,%2,%3}, {%4,%5,%6,%7}, {%8,%9}, {%0,%1,%2,%3};"
        : "+f"(c[0]), "+f"(c[1]), "+f"(c[2]), "+f"(c[3])
        : "r"(a[0]), "r"(a[1]), "r"(a[2]), "r"(a[3]), "r"(b[0]), "r"(b[1]));
}
__device__ __forceinline__ void ldm_x4(uint32_t (&r)[4], uint32_t addr) {
    asm volatile("ldmatrix.sync.aligned.m8n8.x4.shared.b16 {%0,%1,%2,%3}, [%4];"
        : "=r"(r[0]), "=r"(r[1]), "=r"(r[2]), "=r"(r[3]) : "r"(addr));
}
#define CP_ASYNC_CG(dst, src) \
    asm volatile("cp.async.cg.shared.global [%0], [%1], 16;" \
                 :: "r"(dst), "l"(src) : "memory")
#define CP_ASYNC_COMMIT() asm volatile("cp.async.commit_group;" ::: "memory")
#define CP_ASYNC_WAIT1()  asm volatile("cp.async.wait_group 1;" ::: "memory")

// ---------------------------------------------------------------------------
// Pool: warp = one full (b,k1,k2,k3) run of 15 rows -> fixed 15-trip inner
// loop, unroll 5 -> large independent-load batches (MLP). 8.53 loads/row.
// Folded prep (blocks 0..206): Nk table, E = bf16(M-I), pad-row zeroing
// (machinery proven in round 14).
// ---------------------------------------------------------------------------
__global__ void __launch_bounds__(256)
pool_kernel(const float4* __restrict__ vec,
            const float* __restrict__ Acoeff,
            const float* __restrict__ Bbasis,
            const float* __restrict__ Mmat) {
    const int t = threadIdx.x;

    if (blockIdx.x < 207) {              // 207*256 = 52992 prep elements
        int e = blockIdx.x * 256 + t;
        if (e < 32768) {
            int idx = e >> 7, j = e & 127;
            g_nk[e] = Acoeff[j * 256 + idx] * Bbasis[idx * M_DIM + j];
        } else if (e < 49152) {
            int e2 = e - 32768;                    // 0..16383
            int r = e2 >> 7, c = e2 & 127;
            float v = Mmat[e2] - (r == c ? 1.0f : 0.0f);
            g_Eh[e2] = __float2bfloat16_rn(v);
        } else {                                   // zero padded rows
            int z = e - 49152;                     // 0..3839
            int row = ROWS + (z >> 6);
            int w = z & 63;
            if (w < 32) ((uint2*)g_Ah)[(size_t)row * 32 + w] = make_uint2(0u, 0u);
            else        ((uint2*)g_Al)[(size_t)row * 32 + (w - 32)] = make_uint2(0u, 0u);
        }
    }

    const int lane = t & 31;
    const int w = blockIdx.x * 8 + (t >> 5);   // run id
    if (w >= NRUNS) return;
    const int q = lane;                         // float4 channel chunk

    int k3 = w % W_DIM;
    int r1 = w / W_DIM;
    int k2 = r1 % W_DIM;
    int r2 = r1 / W_DIM;
    int k1 = r2 % W_DIM;
    int b  = r2 / W_DIM;

    const int S4 = 32, S3 = 512, S2 = 8192, S1 = 131072;  // float4 strides
    const long long SBATCH = (long long)S1 * D_DIM;
    const float4* p = vec + b * SBATCH + k1 * S1 + k2 * S2 + k3 * S3 + q;
    const int co1 = S3, co2 = S2, co3 = S2 + S3;
    const int co4 = S1, co5 = S1 + S3, co6 = S1 + S2, co7 = S1 + S2 + S3;

    const size_t row0 = (size_t)w * W_DIM;

    float4 sp;
    {
        float sx = 0.f, sy = 0.f, sz = 0.f, sw = 0.f;
        float4 v;
        v = __ldg(p);        sx += v.x; sy += v.y; sz += v.z; sw += v.w;
        v = __ldg(p + co1);  sx += v.x; sy += v.y; sz += v.z; sw += v.w;
        v = __ldg(p + co2);  sx += v.x; sy += v.y; sz += v.z; sw += v.w;
        v = __ldg(p + co3);  sx += v.x; sy += v.y; sz += v.z; sw += v.w;
        v = __ldg(p + co4);  sx += v.x; sy += v.y; sz += v.z; sw += v.w;
        v = __ldg(p + co5);  sx += v.x; sy += v.y; sz += v.z; sw += v.w;
        v = __ldg(p + co6);  sx += v.x; sy += v.y; sz += v.z; sw += v.w;
        v = __ldg(p + co7);  sx += v.x; sy += v.y; sz += v.z; sw += v.w;
        sp = make_float4(sx, sy, sz, sw);
    }
#pragma unroll 5
    for (int j = 1; j <= W_DIM; j++) {
        const float4* pj = p + j * S4;
        float sx = 0.f, sy = 0.f, sz = 0.f, sw = 0.f;
        float4 v;
        v = __ldg(pj);       sx += v.x; sy += v.y; sz += v.z; sw += v.w;
        v = __ldg(pj + co1); sx += v.x; sy += v.y; sz += v.z; sw += v.w;
        v = __ldg(pj + co2); sx += v.x; sy += v.y; sz += v.z; sw += v.w;
        v = __ldg(pj + co3); sx += v.x; sy += v.y; sz += v.z; sw += v.w;
        v = __ldg(pj + co4); sx += v.x; sy += v.y; sz += v.z; sw += v.w;
        v = __ldg(pj + co5); sx += v.x; sy += v.y; sz += v.z; sw += v.w;
        v = __ldg(pj + co6); sx += v.x; sy += v.y; sz += v.z; sw += v.w;
        v = __ldg(pj + co7); sx += v.x; sy += v.y; sz += v.z; sw += v.w;

        float ox = (sp.x + sx) * 0.0625f;
        float oy = (sp.y + sy) * 0.0625f;
        float oz = (sp.z + sz) * 0.0625f;
        float ow = (sp.w + sw) * 0.0625f;
        sp = make_float4(sx, sy, sz, sw);

        uint2 hv, lv;
        split2(ox, oy, hv.x, lv.x);
        split2(oz, ow, hv.y, lv.y);
        size_t orow = (row0 + j - 1) * 32 + q;
        ((uint2*)g_Ah)[orow] = hv;
        ((uint2*)g_Al)[orow] = lv;
    }
}

// ---------------------------------------------------------------------------
// Persistent GEMM (round-15 verbatim, proven at 57.5us):
// acc = A_hi @ E^T (1 bf16 pass); out = Nk - (Ahi+Alo) - acc.
// E once/CTA; A_hi K-halves double-pumped; smem-staged coalesced epilogue.
// ---------------------------------------------------------------------------
#define PITCH_B   272
#define PITCH_A   144
#define PITCH_ST  132
#define OFF_E     0
#define OFF_A0    (128 * PITCH_B)              // 34816
#define OFF_A1    (OFF_A0 + TILE_M * PITCH_A)  // 44032
#define OFF_ST    (OFF_A1 + TILE_M * PITCH_A)  // 53248
#define SMEM_TOTAL (OFF_ST + 32 * PITCH_ST * 4) // 70144

__device__ __forceinline__ void load_a_half(uint32_t sb, int tile, int h, int t) {
    const uint32_t base = (h ? OFF_A1 : OFF_A0);
    const char* ah = (const char*)g_Ah;
    const size_t rowbase = (size_t)tile * TILE_M;
#pragma unroll
    for (int i = 0; i < 2; i++) {
        int e = t + i * 256;            // 0..511
        int r = e >> 3, c = e & 7;      // row 0..63, 16B chunk 0..7
        uint32_t dst = sb + base + (uint32_t)(r * PITCH_A + c * 16);
        size_t src = (rowbase + r) * 256 + (size_t)h * 128 + c * 16;
        CP_ASYNC_CG(dst, ah + src);
    }
}

__global__ void __launch_bounds__(256, 3)
gemm_kernel(float* __restrict__ out) {
    extern __shared__ char smem[];
    const uint32_t sb = smem_u32(smem);
    const int t    = threadIdx.x;
    const int wid  = t >> 5;
    const int lane = t & 31;
    const int wm = wid & 1;
    const int wn = wid >> 1;

    int tile = blockIdx.x;
    {   // prologue: E (once) + first tile's A halves
        const char* eh = (const char*)g_Eh;
#pragma unroll
        for (int i = 0; i < 8; i++) {                  // 2048 chunks
            int e = t + i * 256;
            int r = e >> 4, c = e & 15;
            CP_ASYNC_CG(sb + OFF_E + (uint32_t)(r * PITCH_B + c * 16),
                        eh + r * 256 + c * 16);
        }
        load_a_half(sb, tile, 0, t);
        CP_ASYNC_COMMIT();                             // G: E + A0(t0)
        load_a_half(sb, tile, 1, t);
        CP_ASYNC_COMMIT();                             // G: A1(t0)
    }

    const uint32_t eHi = sb + OFF_E
        + (uint32_t)((wn * 32 + (lane & 7) + (lane >> 4) * 8) * PITCH_B
                     + ((lane >> 3) & 1) * 16);
    const uint32_t a0Frag = sb + OFF_A0
        + (uint32_t)((wm * 32 + (lane & 15)) * PITCH_A + (lane >> 4) * 16);
    const uint32_t a1Frag = a0Frag + (OFF_A1 - OFF_A0);

    const int g  = lane >> 2;
    const int cq = (lane & 3) * 2;

    const char* ahB = (const char*)g_Ah;
    const char* alB = (const char*)g_Al;

    for (; tile < TILES; tile += GRID_GEMM) {
        const int next = tile + GRID_GEMM;
        float acc[2][4][4];
#pragma unroll
        for (int mt = 0; mt < 2; mt++)
#pragma unroll
            for (int nt = 0; nt < 4; nt++)
#pragma unroll
                for (int i = 0; i < 4; i++) acc[mt][nt][i] = 0.f;

        // ---- half 0 (K 0..63) ----
        CP_ASYNC_WAIT1();
        __syncthreads();
#pragma unroll
        for (int ks = 0; ks < 4; ks++) {
            const uint32_t koff = ks * 32;
            uint32_t ah[2][4], ehf[2][4];
            ldm_x4(ah[0], a0Frag + koff);
            ldm_x4(ah[1], a0Frag + 16 * PITCH_A + koff);
            ldm_x4(ehf[0], eHi + koff);
            ldm_x4(ehf[1], eHi + 16 * PITCH_B + koff);
#pragma unroll
            for (int mt = 0; mt < 2; mt++)
#pragma unroll
                for (int nt = 0; nt < 4; nt++)
                    mma_bf16(acc[mt][nt], ah[mt], &ehf[nt >> 1][(nt & 1) * 2]);
        }
        __syncthreads();                       // all warps done reading A0
        if (next < TILES) load_a_half(sb, next, 0, t);
        CP_ASYNC_COMMIT();

        // ---- half 1 (K 64..127) ----
        CP_ASYNC_WAIT1();
        __syncthreads();
#pragma unroll
        for (int ks = 0; ks < 4; ks++) {
            const uint32_t koff = ks * 32;
            const uint32_t kb   = 128 + ks * 32;
            uint32_t ah[2][4], ehf[2][4];
            ldm_x4(ah[0], a1Frag + koff);
            ldm_x4(ah[1], a1Frag + 16 * PITCH_A + koff);
            ldm_x4(ehf[0], eHi + kb);
            ldm_x4(ehf[1], eHi + 16 * PITCH_B + kb);
#pragma unroll
            for (int mt = 0; mt < 2; mt++)
#pragma unroll
                for (int nt = 0; nt < 4; nt++)
                    mma_bf16(acc[mt][nt], ah[mt], &ehf[nt >> 1][(nt & 1) * 2]);
        }
        __syncthreads();                       // all warps done reading A1
        if (next < TILES) load_a_half(sb, next, 1, t);
        CP_ASYNC_COMMIT();

        // ---- epilogue: two 32-row phases; smem-staged, coalesced ----
        const int row0 = tile * TILE_M;
#pragma unroll
        for (int phase = 0; phase < 2; phase++) {
            if (wm == phase) {                 // stage this warp's rows
#pragma unroll
                for (int mt = 0; mt < 2; mt++)
#pragma unroll
                    for (int h8 = 0; h8 < 2; h8++) {
                        int br = mt * 16 + g + h8 * 8;   // 0..31 buffer row
#pragma unroll
                        for (int nt = 0; nt < 4; nt++) {
                            float2 v;
                            v.x = acc[mt][nt][h8 * 2 + 0];
                            v.y = acc[mt][nt][h8 * 2 + 1];
                            *(float2*)(smem + OFF_ST
                                + (br * PITCH_ST + wn * 32 + nt * 8 + cq) * 4) = v;
                        }
                    }
            }
            __syncthreads();
#pragma unroll
            for (int i = 0; i < 2; i++) {
                int e = t + i * 256;           // 0..511
                int r32 = e >> 4, c = e & 15;
                int row = row0 + phase * 32 + r32;
                if (row < ROWS) {
                    int pos = row % POS;
                    int k4 = pos % W_DIM;
                    int q1 = pos / W_DIM;
                    int k3 = q1 % W_DIM;
                    int q2 = q1 / W_DIM;
                    int k2 = q2 % W_DIM;
                    int k1 = q2 / W_DIM;
                    int idx = (((k1 & 3) * 4 + (k2 & 3)) * 4 + (k3 & 3)) * 4
                              + (k4 & 3);
                    const float* nkp = g_nk + idx * M_DIM + c * 8;
                    float4 nk0 = __ldg((const float4*)nkp);
                    float4 nk1 = __ldg((const float4*)(nkp + 4));
                    uint4 ph = __ldcs((const uint4*)(ahB + (size_t)row * 256 + c * 16));
                    uint4 pl = __ldcs((const uint4*)(alB + (size_t)row * 256 + c * 16));
                    const float* st = (const float*)(smem + OFF_ST
                                        + (r32 * PITCH_ST + c * 8) * 4);
                    float2 h0 = bf16x2_to_f2(ph.x), l0 = bf16x2_to_f2(pl.x);
                    float2 h1 = bf16x2_to_f2(ph.y), l1 = bf16x2_to_f2(pl.y);
                    float2 h2 = bf16x2_to_f2(ph.z), l2 = bf16x2_to_f2(pl.z);
                    float2 h3 = bf16x2_to_f2(ph.w), l3 = bf16x2_to_f2(pl.w);
                    float4 o0, o1;
                    o0.x = nk0.x - (h0.x + l0.x) - st[0];
                    o0.y = nk0.y - (h0.y + l0.y) - st[1];
                    o0.z = nk0.z - (h1.x + l1.x) - st[2];
                    o0.w = nk0.w - (h1.y + l1.y) - st[3];
                    o1.x = nk1.x - (h2.x + l2.x) - st[4];
                    o1.y = nk1.y - (h2.y + l2.y) - st[5];
                    o1.z = nk1.z - (h3.x + l3.x) - st[6];
                    o1.w = nk1.w - (h3.y + l3.y) - st[7];
                    float* op = out + (size_t)row * M_DIM + c * 8;
                    __stcs((float4*)op, o0);
                    __stcs((float4*)(op + 4), o1);
                }
            }
            __syncthreads();                   // buffer reuse by next phase
        }
    }
}

// ---------------------------------------------------------------------------
extern "C" void kernel_launch(void* const* d_in, const int* in_sizes, int n_in,
                              void* d_out, int out_size) {
    const float* vec    = (const float*)d_in[0];   // (4,16,16,16,16,128)
    const float* Mmat   = (const float*)d_in[1];   // (128,128)
    const float* Acoeff = (const float*)d_in[2];   // (128,256)
    const float* Bbasis = (const float*)d_in[3];   // (256,128)
    float* out = (float*)d_out;                    // (4, 50625, 128)

    cudaFuncSetAttribute(gemm_kernel,
                         cudaFuncAttributeMaxDynamicSharedMemorySize,
                         SMEM_TOTAL);

    pool_kernel<<<GRID_POOL, 256>>>((const float4*)vec, Acoeff, Bbasis, Mmat);
    gemm_kernel<<<GRID_GEMM, 256, SMEM_TOTAL>>>(out);
}

// round 17
// speedup vs baseline: 1.4349x; 1.0786x over previous
#include <cuda_runtime.h>
#include <cuda_bf16.h>
#include <cstdint>

#define M_DIM 128
#define D_DIM 16
#define W_DIM 15
#define POS   (W_DIM*W_DIM*W_DIM*W_DIM)   // 50625
#define BATCH 4
#define ROWS  (BATCH*POS)                  // 202500
#define TILE_M 64
#define TILES ((ROWS + TILE_M - 1) / TILE_M)   // 3165
#define PADROWS (TILES * TILE_M)               // 202560
#define GRID_GEMM 456                          // 3 CTAs/SM x 152 SMs
#define NSTRIPS (BATCH * W_DIM * W_DIM)        // 900 (b,k1,k2)
#define NGROUPS (NSTRIPS * 5)                  // 4500 warp tasks (3 k3 each)
#define GRID_POOL ((NGROUPS + 7) / 8)          // 563

// Allocation-free scratch (__device__ globals)
__device__ float         g_nk[256 * M_DIM];
__device__ __nv_bfloat16 g_Eh[M_DIM * M_DIM];             // bf16(M - I)
__device__ __nv_bfloat16 g_Ah[(size_t)PADROWS * M_DIM];   // pooled hi
__device__ __nv_bfloat16 g_Al[(size_t)PADROWS * M_DIM];   // pooled lo

// ---------------------------------------------------------------------------
__device__ __forceinline__ uint32_t smem_u32(const void* p) {
    uint32_t a;
    asm("{ .reg .u64 t; cvta.to.shared.u64 t, %1; cvt.u32.u64 %0, t; }"
        : "=r"(a) : "l"(p));
    return a;
}
__device__ __forceinline__ uint32_t pack_bf16(__nv_bfloat16 a, __nv_bfloat16 b) {
    return ((uint32_t)__bfloat16_as_ushort(b) << 16) | __bfloat16_as_ushort(a);
}
__device__ __forceinline__ void split2(float x, float y, uint32_t& hi, uint32_t& lo) {
    __nv_bfloat16 hx = __float2bfloat16_rn(x);
    __nv_bfloat16 hy = __float2bfloat16_rn(y);
    __nv_bfloat16 lx = __float2bfloat16_rn(x - __bfloat162float(hx));
    __nv_bfloat16 ly = __float2bfloat16_rn(y - __bfloat162float(hy));
    hi = pack_bf16(hx, hy);
    lo = pack_bf16(lx, ly);
}
__device__ __forceinline__ float2 bf16x2_to_f2(uint32_t v) {
    __nv_bfloat162 b;
    *(uint32_t*)&b = v;
    return __bfloat1622float2(b);
}
__device__ __forceinline__ void mma_bf16(float* c, const uint32_t* a, const uint32_t* b) {
    asm volatile(
        "mma.sync.aligned.m16n8k16.row.col.f32.bf16.bf16.f32 "
        "{%0,%1,%2,%3}, {%4,%5,%6,%7}, {%8,%9}, {%0,%1,%2,%3};"
        : "+f"(c[0]), "+f"(c[1]), "+f"(c[2]), "+f"(c[3])
        : "r"(a[0]), "r"(a[1]), "r"(a[2]), "r"(a[3]), "r"(b[0]), "r"(b[1]));
}
__device__ __forceinline__ void ldm_x4(uint32_t (&r)[4], uint32_t addr) {
    asm volatile("ldmatrix.sync.aligned.m8n8.x4.shared.b16 {%0,%1,%2,%3}, [%4];"
        : "=r"(r[0]), "=r"(r[1]), "=r"(r[2]), "=r"(r[3]) : "r"(addr));
}
#define CP_ASYNC_CG(dst, src) \
    asm volatile("cp.async.cg.shared.global [%0], [%1], 16;" \
                 :: "r"(dst), "l"(src) : "memory")
#define CP_ASYNC_COMMIT() asm volatile("cp.async.commit_group;" ::: "memory")
#define CP_ASYNC_WAIT1()  asm volatile("cp.async.wait_group 1;" ::: "memory")

// ---------------------------------------------------------------------------
// Pool: warp = (b,k1,k2) strip x 3-k3 group. Per d4-step j: 16 independent
// float4 loads (4 d3-planes x 4 (d1,d2) corners), Pprev[4] rolling regs,
// 3 output rows/step -> 5.69 loads/row (vs 8.53). Fixed trips, unrolled.
// Folded prep (blocks 0..206): Nk, E = bf16(M-I), pad-row zeroing.
// ---------------------------------------------------------------------------
__global__ void __launch_bounds__(256)
pool_kernel(const float4* __restrict__ vec,
            const float* __restrict__ Acoeff,
            const float* __restrict__ Bbasis,
            const float* __restrict__ Mmat) {
    const int t = threadIdx.x;

    if (blockIdx.x < 207) {              // 207*256 = 52992 prep elements
        int e = blockIdx.x * 256 + t;
        if (e < 32768) {
            int idx = e >> 7, j = e & 127;
            g_nk[e] = Acoeff[j * 256 + idx] * Bbasis[idx * M_DIM + j];
        } else if (e < 49152) {
            int e2 = e - 32768;                    // 0..16383
            int r = e2 >> 7, c = e2 & 127;
            float v = Mmat[e2] - (r == c ? 1.0f : 0.0f);
            g_Eh[e2] = __float2bfloat16_rn(v);
        } else {                                   // zero padded rows
            int z = e - 49152;                     // 0..3839
            int row = ROWS + (z >> 6);
            int w = z & 63;
            if (w < 32) ((uint2*)g_Ah)[(size_t)row * 32 + w] = make_uint2(0u, 0u);
            else        ((uint2*)g_Al)[(size_t)row * 32 + (w - 32)] = make_uint2(0u, 0u);
        }
    }

    const int lane = t & 31;
    const int gidx = blockIdx.x * 8 + (t >> 5);    // group id 0..4499
    if (gidx >= NGROUPS) return;
    const int q = lane;                             // float4 channel chunk

    const int cgrp  = gidx % 5;                     // k3 group
    const int strip = gidx / 5;                     // (b,k1,k2)
    int k2 = strip % W_DIM;
    int r1 = strip / W_DIM;
    int k1 = r1 % W_DIM;
    int b  = r1 / W_DIM;

    const int S4 = 32, S3 = 512, S2 = 8192, S1 = 131072;  // float4 strides
    const long long SBATCH = (long long)S1 * D_DIM;
    const float4* base = vec + b * SBATCH + k1 * S1 + k2 * S2
                             + (3 * cgrp) * S3 + q;
    const int cA = S1, cB = S2, cC = S1 + S2;       // (d1,d2) corner offsets

    const size_t rowbase = (size_t)strip * 225 + (size_t)(3 * cgrp) * W_DIM;
    uint2* outH = (uint2*)g_Ah;
    uint2* outL = (uint2*)g_Al;

    float4 Pprev[4];
    // j = 0: prime the 4 plane sums
#pragma unroll
    for (int c3 = 0; c3 < 4; c3++) {
        const float4* p = base + c3 * S3;
        float4 v0 = __ldg(p);
        float4 v1 = __ldg(p + cA);
        float4 v2 = __ldg(p + cB);
        float4 v3 = __ldg(p + cC);
        float4 P;
        P.x = (v0.x + v1.x) + (v2.x + v3.x);
        P.y = (v0.y + v1.y) + (v2.y + v3.y);
        P.z = (v0.z + v1.z) + (v2.z + v3.z);
        P.w = (v0.w + v1.w) + (v2.w + v3.w);
        Pprev[c3] = P;
    }
#pragma unroll 3
    for (int j = 1; j <= W_DIM; j++) {
        float4 P[4];
#pragma unroll
        for (int c3 = 0; c3 < 4; c3++) {
            const float4* p = base + c3 * S3 + j * S4;
            float4 v0 = __ldg(p);
            float4 v1 = __ldg(p + cA);
            float4 v2 = __ldg(p + cB);
            float4 v3 = __ldg(p + cC);
            P[c3].x = (v0.x + v1.x) + (v2.x + v3.x);
            P[c3].y = (v0.y + v1.y) + (v2.y + v3.y);
            P[c3].z = (v0.z + v1.z) + (v2.z + v3.z);
            P[c3].w = (v0.w + v1.w) + (v2.w + v3.w);
        }
#pragma unroll
        for (int i = 0; i < 3; i++) {
            float ox = ((Pprev[i].x + Pprev[i + 1].x)
                        + (P[i].x + P[i + 1].x)) * 0.0625f;
            float oy = ((Pprev[i].y + Pprev[i + 1].y)
                        + (P[i].y + P[i + 1].y)) * 0.0625f;
            float oz = ((Pprev[i].z + Pprev[i + 1].z)
                        + (P[i].z + P[i + 1].z)) * 0.0625f;
            float ow = ((Pprev[i].w + Pprev[i + 1].w)
                        + (P[i].w + P[i + 1].w)) * 0.0625f;
            uint2 hv, lv;
            split2(ox, oy, hv.x, lv.x);
            split2(oz, ow, hv.y, lv.y);
            size_t orow = (rowbase + (size_t)i * W_DIM + (j - 1)) * 32 + q;
            outH[orow] = hv;
            outL[orow] = lv;
        }
#pragma unroll
        for (int c3 = 0; c3 < 4; c3++) Pprev[c3] = P[c3];
    }
}

// ---------------------------------------------------------------------------
// Persistent GEMM (round-16 verbatim, proven at 57.2us):
// acc = A_hi @ E^T (1 bf16 pass); out = Nk - (Ahi+Alo) - acc.
// E once/CTA; A_hi K-halves double-pumped; smem-staged coalesced epilogue.
// ---------------------------------------------------------------------------
#define PITCH_B   272
#define PITCH_A   144
#define PITCH_ST  132
#define OFF_E     0
#define OFF_A0    (128 * PITCH_B)              // 34816
#define OFF_A1    (OFF_A0 + TILE_M * PITCH_A)  // 44032
#define OFF_ST    (OFF_A1 + TILE_M * PITCH_A)  // 53248
#define SMEM_TOTAL (OFF_ST + 32 * PITCH_ST * 4) // 70144

__device__ __forceinline__ void load_a_half(uint32_t sb, int tile, int h, int t) {
    const uint32_t base = (h ? OFF_A1 : OFF_A0);
    const char* ah = (const char*)g_Ah;
    const size_t rowbase = (size_t)tile * TILE_M;
#pragma unroll
    for (int i = 0; i < 2; i++) {
        int e = t + i * 256;            // 0..511
        int r = e >> 3, c = e & 7;      // row 0..63, 16B chunk 0..7
        uint32_t dst = sb + base + (uint32_t)(r * PITCH_A + c * 16);
        size_t src = (rowbase + r) * 256 + (size_t)h * 128 + c * 16;
        CP_ASYNC_CG(dst, ah + src);
    }
}

__global__ void __launch_bounds__(256, 3)
gemm_kernel(float* __restrict__ out) {
    extern __shared__ char smem[];
    const uint32_t sb = smem_u32(smem);
    const int t    = threadIdx.x;
    const int wid  = t >> 5;
    const int lane = t & 31;
    const int wm = wid & 1;
    const int wn = wid >> 1;

    int tile = blockIdx.x;
    {   // prologue: E (once) + first tile's A halves
        const char* eh = (const char*)g_Eh;
#pragma unroll
        for (int i = 0; i < 8; i++) {                  // 2048 chunks
            int e = t + i * 256;
            int r = e >> 4, c = e & 15;
            CP_ASYNC_CG(sb + OFF_E + (uint32_t)(r * PITCH_B + c * 16),
                        eh + r * 256 + c * 16);
        }
        load_a_half(sb, tile, 0, t);
        CP_ASYNC_COMMIT();                             // G: E + A0(t0)
        load_a_half(sb, tile, 1, t);
        CP_ASYNC_COMMIT();                             // G: A1(t0)
    }

    const uint32_t eHi = sb + OFF_E
        + (uint32_t)((wn * 32 + (lane & 7) + (lane >> 4) * 8) * PITCH_B
                     + ((lane >> 3) & 1) * 16);
    const uint32_t a0Frag = sb + OFF_A0
        + (uint32_t)((wm * 32 + (lane & 15)) * PITCH_A + (lane >> 4) * 16);
    const uint32_t a1Frag = a0Frag + (OFF_A1 - OFF_A0);

    const int g  = lane >> 2;
    const int cq = (lane & 3) * 2;

    const char* ahB = (const char*)g_Ah;
    const char* alB = (const char*)g_Al;

    for (; tile < TILES; tile += GRID_GEMM) {
        const int next = tile + GRID_GEMM;
        float acc[2][4][4];
#pragma unroll
        for (int mt = 0; mt < 2; mt++)
#pragma unroll
            for (int nt = 0; nt < 4; nt++)
#pragma unroll
                for (int i = 0; i < 4; i++) acc[mt][nt][i] = 0.f;

        // ---- half 0 (K 0..63) ----
        CP_ASYNC_WAIT1();
        __syncthreads();
#pragma unroll
        for (int ks = 0; ks < 4; ks++) {
            const uint32_t koff = ks * 32;
            uint32_t ah[2][4], ehf[2][4];
            ldm_x4(ah[0], a0Frag + koff);
            ldm_x4(ah[1], a0Frag + 16 * PITCH_A + koff);
            ldm_x4(ehf[0], eHi + koff);
            ldm_x4(ehf[1], eHi + 16 * PITCH_B + koff);
#pragma unroll
            for (int mt = 0; mt < 2; mt++)
#pragma unroll
                for (int nt = 0; nt < 4; nt++)
                    mma_bf16(acc[mt][nt], ah[mt], &ehf[nt >> 1][(nt & 1) * 2]);
        }
        __syncthreads();                       // all warps done reading A0
        if (next < TILES) load_a_half(sb, next, 0, t);
        CP_ASYNC_COMMIT();

        // ---- half 1 (K 64..127) ----
        CP_ASYNC_WAIT1();
        __syncthreads();
#pragma unroll
        for (int ks = 0; ks < 4; ks++) {
            const uint32_t koff = ks * 32;
            const uint32_t kb   = 128 + ks * 32;
            uint32_t ah[2][4], ehf[2][4];
            ldm_x4(ah[0], a1Frag + koff);
            ldm_x4(ah[1], a1Frag + 16 * PITCH_A + koff);
            ldm_x4(ehf[0], eHi + kb);
            ldm_x4(ehf[1], eHi + 16 * PITCH_B + kb);
#pragma unroll
            for (int mt = 0; mt < 2; mt++)
#pragma unroll
                for (int nt = 0; nt < 4; nt++)
                    mma_bf16(acc[mt][nt], ah[mt], &ehf[nt >> 1][(nt & 1) * 2]);
        }
        __syncthreads();                       // all warps done reading A1
        if (next < TILES) load_a_half(sb, next, 1, t);
        CP_ASYNC_COMMIT();

        // ---- epilogue: two 32-row phases; smem-staged, coalesced ----
        const int row0 = tile * TILE_M;
#pragma unroll
        for (int phase = 0; phase < 2; phase++) {
            if (wm == phase) {                 // stage this warp's rows
#pragma unroll
                for (int mt = 0; mt < 2; mt++)
#pragma unroll
                    for (int h8 = 0; h8 < 2; h8++) {
                        int br = mt * 16 + g + h8 * 8;   // 0..31 buffer row
#pragma unroll
                        for (int nt = 0; nt < 4; nt++) {
                            float2 v;
                            v.x = acc[mt][nt][h8 * 2 + 0];
                            v.y = acc[mt][nt][h8 * 2 + 1];
                            *(float2*)(smem + OFF_ST
                                + (br * PITCH_ST + wn * 32 + nt * 8 + cq) * 4) = v;
                        }
                    }
            }
            __syncthreads();
#pragma unroll
            for (int i = 0; i < 2; i++) {
                int e = t + i * 256;           // 0..511
                int r32 = e >> 4, c = e & 15;
                int row = row0 + phase * 32 + r32;
                if (row < ROWS) {
                    int pos = row % POS;
                    int k4 = pos % W_DIM;
                    int q1 = pos / W_DIM;
                    int k3 = q1 % W_DIM;
                    int q2 = q1 / W_DIM;
                    int k2 = q2 % W_DIM;
                    int k1 = q2 / W_DIM;
                    int idx = (((k1 & 3) * 4 + (k2 & 3)) * 4 + (k3 & 3)) * 4
                              + (k4 & 3);
                    const float* nkp = g_nk + idx * M_DIM + c * 8;
                    float4 nk0 = __ldg((const float4*)nkp);
                    float4 nk1 = __ldg((const float4*)(nkp + 4));
                    uint4 ph = __ldcs((const uint4*)(ahB + (size_t)row * 256 + c * 16));
                    uint4 pl = __ldcs((const uint4*)(alB + (size_t)row * 256 + c * 16));
                    const float* st = (const float*)(smem + OFF_ST
                                        + (r32 * PITCH_ST + c * 8) * 4);
                    float2 h0 = bf16x2_to_f2(ph.x), l0 = bf16x2_to_f2(pl.x);
                    float2 h1 = bf16x2_to_f2(ph.y), l1 = bf16x2_to_f2(pl.y);
                    float2 h2 = bf16x2_to_f2(ph.z), l2 = bf16x2_to_f2(pl.z);
                    float2 h3 = bf16x2_to_f2(ph.w), l3 = bf16x2_to_f2(pl.w);
                    float4 o0, o1;
                    o0.x = nk0.x - (h0.x + l0.x) - st[0];
                    o0.y = nk0.y - (h0.y + l0.y) - st[1];
                    o0.z = nk0.z - (h1.x + l1.x) - st[2];
                    o0.w = nk0.w - (h1.y + l1.y) - st[3];
                    o1.x = nk1.x - (h2.x + l2.x) - st[4];
                    o1.y = nk1.y - (h2.y + l2.y) - st[5];
                    o1.z = nk1.z - (h3.x + l3.x) - st[6];
                    o1.w = nk1.w - (h3.y + l3.y) - st[7];
                    float* op = out + (size_t)row * M_DIM + c * 8;
                    __stcs((float4*)op, o0);
                    __stcs((float4*)(op + 4), o1);
                }
            }
            __syncthreads();                   // buffer reuse by next phase
        }
    }
}

// ---------------------------------------------------------------------------
extern "C" void kernel_launch(void* const* d_in, const int* in_sizes, int n_in,
                              void* d_out, int out_size) {
    const float* vec    = (const float*)d_in[0];   // (4,16,16,16,16,128)
    const float* Mmat   = (const float*)d_in[1];   // (128,128)
    const float* Acoeff = (const float*)d_in[2];   // (128,256)
    const float* Bbasis = (const float*)d_in[3];   // (256,128)
    float* out = (float*)d_out;                    // (4, 50625, 128)

    cudaFuncSetAttribute(gemm_kernel,
                         cudaFuncAttributeMaxDynamicSharedMemorySize,
                         SMEM_TOTAL);

    pool_kernel<<<GRID_POOL, 256>>>((const float4*)vec, Acoeff, Bbasis, Mmat);
    gemm_kernel<<<GRID_GEMM, 256, SMEM_TOTAL>>>(out);
}